// round 2
// baseline (speedup 1.0000x reference)
#include <cuda_runtime.h>
#include <cuda_bf16.h>

// Problem constants: B=4, H=W=64 -> N=4096, C=64, Cf=8
#define BATCH 4
#define NTOK  4096
#define CDIM  64
#define CF    8
#define BN    (BATCH * NTOK)   // 16384 rows

// ---------------- scratch (no cudaMalloc allowed) ----------------
__device__ float d_fbuf[BN * CF];    // keys     [B,N,8]
__device__ float d_gbuf[BN * CF];    // queries  [B,N,8]
__device__ float d_hbuf[BN * CDIM];  // values   [B,N,64]

// ---------------- packed f32x2 helpers ----------------
__device__ __forceinline__ unsigned long long ffma2(unsigned long long a,
                                                    unsigned long long b,
                                                    unsigned long long c) {
    unsigned long long d;
    asm("fma.rn.f32x2 %0, %1, %2, %3;" : "=l"(d) : "l"(a), "l"(b), "l"(c));
    return d;
}
__device__ __forceinline__ unsigned long long pk2(float x, float y) {
    unsigned long long r;
    asm("mov.b64 %0, {%1, %2};" : "=l"(r) : "f"(x), "f"(y));
    return r;
}
__device__ __forceinline__ float2 upk2(unsigned long long v) {
    float2 r;
    asm("mov.b64 {%0, %1}, %2;" : "=f"(r.x), "=f"(r.y) : "l"(v));
    return r;
}

// ---------------- kernel 1: fused projections f,g,h ----------------
// grid: BN/32 blocks of 256 threads; each block does 32 rows x 80 channels.
__global__ void proj_kernel(const float* __restrict__ x,
                            const float* __restrict__ w_f, const float* __restrict__ b_f,
                            const float* __restrict__ w_g, const float* __restrict__ b_g,
                            const float* __restrict__ w_h, const float* __restrict__ b_h) {
    __shared__ float wf_s[CDIM * CF];
    __shared__ float wg_s[CDIM * CF];
    __shared__ float wh_s[CDIM * CDIM];
    __shared__ float bf_s[CF], bg_s[CF], bh_s[CDIM];
    __shared__ float xs[32][CDIM];

    const int tid = threadIdx.x;
    for (int i = tid; i < CDIM * CF; i += 256) { wf_s[i] = w_f[i]; wg_s[i] = w_g[i]; }
    for (int i = tid; i < CDIM * CDIM; i += 256) wh_s[i] = w_h[i];
    if (tid < CF)   { bf_s[tid] = b_f[tid]; bg_s[tid] = b_g[tid]; }
    if (tid < CDIM) bh_s[tid] = b_h[tid];

    const int row0 = blockIdx.x * 32;
    for (int i = tid; i < 32 * CDIM; i += 256)
        xs[i / CDIM][i % CDIM] = x[(row0 + i / CDIM) * CDIM + (i % CDIM)];
    __syncthreads();

    // 32 rows x 80 channels = 2560 outputs, 10 per thread
    for (int idx = tid; idx < 32 * 80; idx += 256) {
        const int r = idx / 80, c = idx % 80;
        const float* w; float bias; float* outp; int stride;
        if (c < 8)       { w = wf_s + c;        bias = bf_s[c];      outp = d_fbuf + (row0 + r) * CF + c;        stride = CF;   }
        else if (c < 16) { w = wg_s + (c - 8);  bias = bg_s[c - 8];  outp = d_gbuf + (row0 + r) * CF + (c - 8);  stride = CF;   }
        else             { w = wh_s + (c - 16); bias = bh_s[c - 16]; outp = d_hbuf + (row0 + r) * CDIM + (c - 16); stride = CDIM; }
        float acc = bias;
        #pragma unroll
        for (int k = 0; k < CDIM; k++) acc += xs[r][k] * w[k * stride];
        *outp = acc;
    }
}

// ---------------- kernel 2: streaming attention ----------------
// One thread owns one query (all 64 output channels in registers).
// Block = 128 threads = 128 queries. Grid = (NTOK/128, BATCH) = (32,4).
// Key tiles of 128 staged through shared memory.
// No online max needed: scores bounded (|s| < ~10), exp(s) safe in fp32.
#define KT 128

__global__ __launch_bounds__(128, 1)
void attn_kernel(const float* __restrict__ x,
                 const float* __restrict__ gamma,
                 float* __restrict__ out) {
    __shared__ __align__(16) float fS[KT * CF];     // 4 KB
    __shared__ __align__(16) float hS[KT * CDIM];   // 32 KB

    const int b   = blockIdx.y;
    const int q   = blockIdx.x * 128 + threadIdx.x;
    const int row = b * NTOK + q;

    // load this thread's query vector g[8], packed as 4 f32x2
    unsigned long long gp[4];
    {
        const unsigned long long* gsrc =
            reinterpret_cast<const unsigned long long*>(d_gbuf + row * CF);
        #pragma unroll
        for (int i = 0; i < 4; i++) gp[i] = gsrc[i];
    }

    unsigned long long acc[CDIM / 2];
    const unsigned long long zz = pk2(0.0f, 0.0f);
    #pragma unroll
    for (int c = 0; c < CDIM / 2; c++) acc[c] = zz;
    float l = 0.0f;

    for (int kt = 0; kt < NTOK; kt += KT) {
        __syncthreads();
        // stage f tile: KT*8 floats = 256 float4, 2 per thread
        {
            const float4* fsrc = reinterpret_cast<const float4*>(d_fbuf + (b * NTOK + kt) * CF);
            float4* fdst = reinterpret_cast<float4*>(fS);
            fdst[threadIdx.x]       = fsrc[threadIdx.x];
            fdst[threadIdx.x + 128] = fsrc[threadIdx.x + 128];
        }
        // stage h tile: KT*64 floats = 2048 float4, 16 per thread
        {
            const float4* hsrc = reinterpret_cast<const float4*>(d_hbuf + (b * NTOK + kt) * CDIM);
            float4* hdst = reinterpret_cast<float4*>(hS);
            #pragma unroll
            for (int i = 0; i < 16; i++)
                hdst[threadIdx.x + i * 128] = hsrc[threadIdx.x + i * 128];
        }
        __syncthreads();

        #pragma unroll 4
        for (int k = 0; k < KT; k++) {
            // score = <g, f_k> over 8 dims via packed fma
            const unsigned long long* fp =
                reinterpret_cast<const unsigned long long*>(fS + k * CF);
            unsigned long long s2 = zz;
            #pragma unroll
            for (int i = 0; i < 4; i++) s2 = ffma2(gp[i], fp[i], s2);
            const float2 sh = upk2(s2);
            const float  s  = sh.x + sh.y;
            const float  p  = __expf(s);
            l += p;
            const unsigned long long pp = pk2(p, p);
            // acc += p * h_k (32 packed FMAs, broadcast LDS.128 from smem)
            const ulonglong2* hp = reinterpret_cast<const ulonglong2*>(hS + k * CDIM);
            #pragma unroll
            for (int c = 0; c < CDIM / 4; c++) {
                const ulonglong2 hv = hp[c];
                acc[2 * c]     = ffma2(pp, hv.x, acc[2 * c]);
                acc[2 * c + 1] = ffma2(pp, hv.y, acc[2 * c + 1]);
            }
        }
    }

    // epilogue: out = gamma * acc / l + x
    const float gm = gamma[0] / l;
    const float* xr = x + row * CDIM;
    float* orow = out + row * CDIM;
    #pragma unroll
    for (int c = 0; c < CDIM / 2; c++) {
        const float2 a = upk2(acc[c]);
        orow[2 * c]     = fmaf(gm, a.x, xr[2 * c]);
        orow[2 * c + 1] = fmaf(gm, a.y, xr[2 * c + 1]);
    }
}

// ---------------- launch ----------------
extern "C" void kernel_launch(void* const* d_in, const int* in_sizes, int n_in,
                              void* d_out, int out_size) {
    const float* x     = (const float*)d_in[0];
    const float* w_f   = (const float*)d_in[1];
    const float* b_f   = (const float*)d_in[2];
    const float* w_g   = (const float*)d_in[3];
    const float* b_g   = (const float*)d_in[4];
    const float* w_h   = (const float*)d_in[5];
    const float* b_h   = (const float*)d_in[6];
    const float* gamma = (const float*)d_in[7];
    float* out = (float*)d_out;

    proj_kernel<<<BN / 32, 256>>>(x, w_f, b_f, w_g, b_g, w_h, b_h);
    attn_kernel<<<dim3(NTOK / 128, BATCH), 128>>>(x, gamma, out);
}

// round 5
// speedup vs baseline: 3.9155x; 3.9155x over previous
#include <cuda_runtime.h>
#include <cuda_bf16.h>
#include <cstdint>

// Problem: B=4, N=4096 (64x64), C=64, Cf=8
#define BATCH 4
#define NTOK  4096
#define CDIM  64
#define CF    8
#define BN    (BATCH * NTOK)
#define KT    64               // keys per tile
#define NTILE (NTOK / KT)      // 64

// ---------------- scratch (no cudaMalloc allowed) ----------------
__device__ __nv_bfloat16 d_fb[BN * CF];              // keys    [B,N,8]
__device__ __nv_bfloat16 d_gb[BN * CF];              // queries [B,N,8]
__device__ __nv_bfloat16 d_htb[BATCH * CDIM * NTOK]; // values transposed [B,C,N]

// m16n8k16 bf16 MMA (row.col), f32 accumulate
#define MMA16816(d, a0, a1, a2, a3, b0, b1, c) \
    asm volatile("mma.sync.aligned.m16n8k16.row.col.f32.bf16.bf16.f32 " \
        "{%0,%1,%2,%3}, {%4,%5,%6,%7}, {%8,%9}, {%10,%11,%12,%13};" \
        : "=f"((d)[0]), "=f"((d)[1]), "=f"((d)[2]), "=f"((d)[3]) \
        : "r"(a0), "r"(a1), "r"(a2), "r"(a3), "r"(b0), "r"(b1), \
          "f"((c)[0]), "f"((c)[1]), "f"((c)[2]), "f"((c)[3]))

#define CVT_BF16X2(res, lo, hi) \
    asm("cvt.rn.bf16x2.f32 %0, %1, %2;" : "=r"(res) : "f"(hi), "f"(lo))

// ---------------- kernel 1: fused projections -> bf16 ----------------
// block = 256 threads, 32 rows; h goes through smem for coalesced transposed store.
__global__ void proj_kernel(const float* __restrict__ x,
                            const float* __restrict__ w_f, const float* __restrict__ b_f,
                            const float* __restrict__ w_g, const float* __restrict__ b_g,
                            const float* __restrict__ w_h, const float* __restrict__ b_h) {
    __shared__ float wf_s[CDIM * CF];
    __shared__ float wg_s[CDIM * CF];
    __shared__ float wh_s[CDIM * CDIM];
    __shared__ float bf_s[CF], bg_s[CF], bh_s[CDIM];
    __shared__ float xs[32][CDIM];
    __shared__ float hs[CDIM][33];    // transposed h staging [ch][n], pad 33

    const int tid = threadIdx.x;
    for (int i = tid; i < CDIM * CF; i += 256) { wf_s[i] = w_f[i]; wg_s[i] = w_g[i]; }
    for (int i = tid; i < CDIM * CDIM; i += 256) wh_s[i] = w_h[i];
    if (tid < CF)   { bf_s[tid] = b_f[tid]; bg_s[tid] = b_g[tid]; }
    if (tid < CDIM) bh_s[tid] = b_h[tid];

    const int row0 = blockIdx.x * 32;
    for (int i = tid; i < 32 * CDIM; i += 256)
        xs[i / CDIM][i % CDIM] = x[(row0 + i / CDIM) * CDIM + (i % CDIM)];
    __syncthreads();

    for (int idx = tid; idx < 32 * 80; idx += 256) {
        const int r = idx / 80, c = idx % 80;
        const float* w; float bias; int stride;
        if (c < 8)       { w = wf_s + c;        bias = bf_s[c];      stride = CF;   }
        else if (c < 16) { w = wg_s + (c - 8);  bias = bg_s[c - 8];  stride = CF;   }
        else             { w = wh_s + (c - 16); bias = bh_s[c - 16]; stride = CDIM; }
        float acc = bias;
        #pragma unroll
        for (int k = 0; k < CDIM; k++) acc += xs[r][k] * w[k * stride];
        const int row = row0 + r;
        if (c < 8)       d_fb[row * CF + c] = __float2bfloat16(acc);
        else if (c < 16) d_gb[row * CF + (c - 8)] = __float2bfloat16(acc);
        else             hs[c - 16][r] = acc;
    }
    __syncthreads();

    // coalesced transposed store of h: thread t -> ch = t/4, 8 keys per store
    {
        const int b  = row0 >> 12;
        const int n0 = row0 & (NTOK - 1);
        const int ch = tid >> 2;
        const int part = (tid & 3) * 8;
        __nv_bfloat16 v[8];
        #pragma unroll
        for (int j = 0; j < 8; j++) v[j] = __float2bfloat16(hs[ch][part + j]);
        *reinterpret_cast<uint4*>(d_htb + ((size_t)b * CDIM + ch) * NTOK + n0 + part) =
            *reinterpret_cast<const uint4*>(v);
    }
}

// ---------------- kernel 2: HMMA flash attention ----------------
// 8 warps x 16 queries = 128 queries per CTA. Grid (32, 4).
// Per 64-key tile: S = G@F^T (8 mma, K padded 8->16), exp in regs,
// S-frag layout == P A-frag layout (zero shuffles), O += P@H^T (32 mma).
__global__ __launch_bounds__(256, 1)
void attn_kernel(const float* __restrict__ x,
                 const float* __restrict__ gamma,
                 float* __restrict__ out) {
    __shared__ __nv_bfloat16 fS[KT * CF];        // [key][c], 16 B rows
    __shared__ __nv_bfloat16 hS[CDIM * 72];      // [ch][key], pitch 72 (conflict-free)

    const int tid  = threadIdx.x;
    const int warp = tid >> 5;
    const int lane = tid & 31;
    const int gid  = lane >> 2;    // group id 0..7
    const int tig  = lane & 3;     // thread in group 0..3

    const int b    = blockIdx.y;
    const int q0   = blockIdx.x * 128 + warp * 16;
    const int row0 = b * NTOK + q0;

    // G A-fragment (constant across tiles): a2=a3=0 pads K 8->16
    const uint32_t ga0 = *reinterpret_cast<const uint32_t*>(d_gb + (row0 + gid) * CF + tig * 2);
    const uint32_t ga1 = *reinterpret_cast<const uint32_t*>(d_gb + (row0 + 8 + gid) * CF + tig * 2);

    float O[8][4];
    #pragma unroll
    for (int n = 0; n < 8; n++)
        #pragma unroll
        for (int j = 0; j < 4; j++) O[n][j] = 0.0f;
    float l0 = 0.0f, l1 = 0.0f;
    const float zc[4] = {0.0f, 0.0f, 0.0f, 0.0f};

    for (int t = 0; t < NTILE; t++) {
        __syncthreads();
        // stage F tile: 64 rows x 16 B
        if (tid < 64) {
            reinterpret_cast<uint4*>(fS)[tid] =
                reinterpret_cast<const uint4*>(d_fb + (size_t)(b * NTOK + t * KT) * CF)[tid];
        }
        // stage H^T tile: 64 ch x 64 keys (128 B per row, pitch 144 B in smem)
        #pragma unroll
        for (int i = tid; i < 512; i += 256) {
            const int ch = i >> 3, ck = i & 7;
            const uint4 v = *reinterpret_cast<const uint4*>(
                d_htb + ((size_t)b * CDIM + ch) * NTOK + t * KT + ck * 8);
            *reinterpret_cast<uint4*>(hS + ch * 72 + ck * 8) = v;
        }
        __syncthreads();

        // --- QK: S[16q x 64k], 8 n-tiles ---
        float S[8][4];
        #pragma unroll
        for (int n = 0; n < 8; n++) {
            const uint32_t fb0 = *reinterpret_cast<const uint32_t*>(
                fS + (n * 8 + gid) * CF + tig * 2);
            MMA16816(S[n], ga0, ga1, 0u, 0u, fb0, 0u, zc);
        }

        // --- exp + row sums + pack P fragments (bf16x2) ---
        uint32_t P[8][2];
        #pragma unroll
        for (int n = 0; n < 8; n++) {
            const float e0 = __expf(S[n][0]);
            const float e1 = __expf(S[n][1]);
            const float e2 = __expf(S[n][2]);
            const float e3 = __expf(S[n][3]);
            l0 += e0 + e1;
            l1 += e2 + e3;
            CVT_BF16X2(P[n][0], e0, e1);   // row gid,   cols 2tig,2tig+1
            CVT_BF16X2(P[n][1], e2, e3);   // row gid+8
        }

        // --- PV: O[16q x 64c] += P @ H^T, K=64 in 4 chunks of 16 ---
        #pragma unroll
        for (int kk = 0; kk < 4; kk++) {
            const uint32_t a0 = P[2 * kk][0];
            const uint32_t a1 = P[2 * kk][1];
            const uint32_t a2 = P[2 * kk + 1][0];
            const uint32_t a3 = P[2 * kk + 1][1];
            #pragma unroll
            for (int nch = 0; nch < 8; nch++) {
                const __nv_bfloat16* hp = hS + (nch * 8 + gid) * 72 + kk * 16 + tig * 2;
                const uint32_t b0 = *reinterpret_cast<const uint32_t*>(hp);
                const uint32_t b1 = *reinterpret_cast<const uint32_t*>(hp + 8);
                MMA16816(O[nch], a0, a1, a2, a3, b0, b1, O[nch]);
            }
        }
    }

    // reduce row sums across the 4 lanes of each row group
    l0 += __shfl_xor_sync(0xFFFFFFFF, l0, 1);
    l0 += __shfl_xor_sync(0xFFFFFFFF, l0, 2);
    l1 += __shfl_xor_sync(0xFFFFFFFF, l1, 1);
    l1 += __shfl_xor_sync(0xFFFFFFFF, l1, 2);

    const float gm   = gamma[0];
    const float inv0 = gm / l0;
    const float inv1 = gm / l1;

    // epilogue: out = gamma * O / l + x
    const size_t base0 = (size_t)(row0 + gid) * CDIM;
    const size_t base1 = (size_t)(row0 + 8 + gid) * CDIM;
    #pragma unroll
    for (int n = 0; n < 8; n++) {
        const int ch = n * 8 + tig * 2;
        const float2 xv0 = *reinterpret_cast<const float2*>(x + base0 + ch);
        const float2 xv1 = *reinterpret_cast<const float2*>(x + base1 + ch);
        float2 o0, o1;
        o0.x = fmaf(inv0, O[n][0], xv0.x);
        o0.y = fmaf(inv0, O[n][1], xv0.y);
        o1.x = fmaf(inv1, O[n][2], xv1.x);
        o1.y = fmaf(inv1, O[n][3], xv1.y);
        *reinterpret_cast<float2*>(out + base0 + ch) = o0;
        *reinterpret_cast<float2*>(out + base1 + ch) = o1;
    }
}

// ---------------- launch ----------------
extern "C" void kernel_launch(void* const* d_in, const int* in_sizes, int n_in,
                              void* d_out, int out_size) {
    const float* x     = (const float*)d_in[0];
    const float* w_f   = (const float*)d_in[1];
    const float* b_f   = (const float*)d_in[2];
    const float* w_g   = (const float*)d_in[3];
    const float* b_g   = (const float*)d_in[4];
    const float* w_h   = (const float*)d_in[5];
    const float* b_h   = (const float*)d_in[6];
    const float* gamma = (const float*)d_in[7];
    float* out = (float*)d_out;

    proj_kernel<<<BN / 32, 256>>>(x, w_f, b_f, w_g, b_g, w_h, b_h);
    attn_kernel<<<dim3(NTOK / 128, BATCH), 256>>>(x, gamma, out);
}

// round 8
// speedup vs baseline: 4.8436x; 1.2370x over previous
#include <cuda_runtime.h>
#include <cuda_bf16.h>
#include <cstdint>

// Problem: B=4, N=4096 (64x64), C=64, Cf=8
#define BATCH 4
#define NTOK  4096
#define CDIM  64
#define CF    8
#define BN    (BATCH * NTOK)
#define KT    64               // keys per tile
#define NTILE (NTOK / KT)      // 64
#define QPC   64               // queries per CTA (4 warps x 16)

// ---------------- scratch (no cudaMalloc allowed) ----------------
__device__ __nv_bfloat16 d_fb[BN * CF];              // keys    [B,N,8]
__device__ __nv_bfloat16 d_gb[BN * CF];              // queries [B,N,8]
__device__ __nv_bfloat16 d_htb[BATCH * CDIM * NTOK]; // values transposed [B,C,N]

// m16n8k16 bf16 MMA (row.col), f32 accumulate
#define MMA16816(d, a0, a1, a2, a3, b0, b1, c) \
    asm volatile("mma.sync.aligned.m16n8k16.row.col.f32.bf16.bf16.f32 " \
        "{%0,%1,%2,%3}, {%4,%5,%6,%7}, {%8,%9}, {%10,%11,%12,%13};" \
        : "=f"((d)[0]), "=f"((d)[1]), "=f"((d)[2]), "=f"((d)[3]) \
        : "r"(a0), "r"(a1), "r"(a2), "r"(a3), "r"(b0), "r"(b1), \
          "f"((c)[0]), "f"((c)[1]), "f"((c)[2]), "f"((c)[3]))

// m16n8k8 bf16 MMA (row.col) — exact fit for Cf=8, no zero padding
#define MMA1688(d, a0, a1, b0, c) \
    asm volatile("mma.sync.aligned.m16n8k8.row.col.f32.bf16.bf16.f32 " \
        "{%0,%1,%2,%3}, {%4,%5}, {%6}, {%7,%8,%9,%10};" \
        : "=f"((d)[0]), "=f"((d)[1]), "=f"((d)[2]), "=f"((d)[3]) \
        : "r"(a0), "r"(a1), "r"(b0), \
          "f"((c)[0]), "f"((c)[1]), "f"((c)[2]), "f"((c)[3]))

#define CVT_BF16X2(res, lo, hi) \
    asm("cvt.rn.bf16x2.f32 %0, %1, %2;" : "=r"(res) : "f"(hi), "f"(lo))

__device__ __forceinline__ void cp16(void* dst, const void* src) {
    const uint32_t d = (uint32_t)__cvta_generic_to_shared(dst);
    asm volatile("cp.async.cg.shared.global [%0], [%1], 16;" :: "r"(d), "l"(src));
}
#define CP_COMMIT() asm volatile("cp.async.commit_group;" ::: "memory")
#define CP_WAIT0()  asm volatile("cp.async.wait_group 0;" ::: "memory")

// ---------------- kernel 1: fused projections -> bf16 ----------------
__global__ void proj_kernel(const float* __restrict__ x,
                            const float* __restrict__ w_f, const float* __restrict__ b_f,
                            const float* __restrict__ w_g, const float* __restrict__ b_g,
                            const float* __restrict__ w_h, const float* __restrict__ b_h) {
    __shared__ float wf_s[CDIM * CF];
    __shared__ float wg_s[CDIM * CF];
    __shared__ float wh_s[CDIM * CDIM];
    __shared__ float bf_s[CF], bg_s[CF], bh_s[CDIM];
    __shared__ float xs[32][CDIM];
    __shared__ float hs[CDIM][33];    // transposed h staging [ch][n]

    const int tid = threadIdx.x;
    for (int i = tid; i < CDIM * CF; i += 256) { wf_s[i] = w_f[i]; wg_s[i] = w_g[i]; }
    for (int i = tid; i < CDIM * CDIM; i += 256) wh_s[i] = w_h[i];
    if (tid < CF)   { bf_s[tid] = b_f[tid]; bg_s[tid] = b_g[tid]; }
    if (tid < CDIM) bh_s[tid] = b_h[tid];

    const int row0 = blockIdx.x * 32;
    for (int i = tid; i < 32 * CDIM; i += 256)
        xs[i / CDIM][i % CDIM] = x[(row0 + i / CDIM) * CDIM + (i % CDIM)];
    __syncthreads();

    for (int idx = tid; idx < 32 * 80; idx += 256) {
        const int r = idx / 80, c = idx % 80;
        const float* w; float bias; int stride;
        if (c < 8)       { w = wf_s + c;        bias = bf_s[c];      stride = CF;   }
        else if (c < 16) { w = wg_s + (c - 8);  bias = bg_s[c - 8];  stride = CF;   }
        else             { w = wh_s + (c - 16); bias = bh_s[c - 16]; stride = CDIM; }
        float acc = bias;
        #pragma unroll
        for (int k = 0; k < CDIM; k++) acc += xs[r][k] * w[k * stride];
        const int row = row0 + r;
        if (c < 8)       d_fb[row * CF + c] = __float2bfloat16(acc);
        else if (c < 16) d_gb[row * CF + (c - 8)] = __float2bfloat16(acc);
        else             hs[c - 16][r] = acc;
    }
    __syncthreads();

    {
        const int b  = row0 >> 12;
        const int n0 = row0 & (NTOK - 1);
        const int ch = tid >> 2;
        const int part = (tid & 3) * 8;
        __nv_bfloat16 v[8];
        #pragma unroll
        for (int j = 0; j < 8; j++) v[j] = __float2bfloat16(hs[ch][part + j]);
        *reinterpret_cast<uint4*>(d_htb + ((size_t)b * CDIM + ch) * NTOK + n0 + part) =
            *reinterpret_cast<const uint4*>(v);
    }
}

// ---------------- kernel 2: HMMA flash attention, cp.async pipelined ----
// 4 warps x 16 queries = 64 queries per CTA. Grid (64, 4) = 256 CTAs (~2/SM).
// Double-buffered F/H tiles via cp.async; load(t+1) overlaps compute(t).
__global__ __launch_bounds__(128, 2)
void attn_kernel(const float* __restrict__ x,
                 const float* __restrict__ gamma,
                 float* __restrict__ out) {
    __shared__ __nv_bfloat16 fS[2][KT * CF];     // [buf][key][c], 1 KB each
    __shared__ __nv_bfloat16 hS[2][CDIM * 72];   // [buf][ch][key], pitch 72, 9 KB each

    const int tid  = threadIdx.x;
    const int warp = tid >> 5;
    const int lane = tid & 31;
    const int gid  = lane >> 2;
    const int tig  = lane & 3;

    const int b    = blockIdx.y;
    const int q0   = blockIdx.x * QPC + warp * 16;
    const int row0 = b * NTOK + q0;

    // G A-fragment, constant across tiles (K=8 exact for m16n8k8)
    const uint32_t ga0 = *reinterpret_cast<const uint32_t*>(d_gb + (row0 + gid) * CF + tig * 2);
    const uint32_t ga1 = *reinterpret_cast<const uint32_t*>(d_gb + (row0 + 8 + gid) * CF + tig * 2);

    float O[8][4];
    #pragma unroll
    for (int n = 0; n < 8; n++)
        #pragma unroll
        for (int j = 0; j < 4; j++) O[n][j] = 0.0f;
    float l0 = 0.0f, l1 = 0.0f;
    const float zc[4] = {0.0f, 0.0f, 0.0f, 0.0f};

    // tile loader: F = 64 x 16B (threads 0..63), H = 512 x 16B (4/thread)
    auto load_tile = [&](int t) {
        const int buf = t & 1;
        if (tid < 64)
            cp16(&fS[buf][tid * CF], d_fb + (size_t)(b * NTOK + t * KT + tid) * CF);
        const __nv_bfloat16* hsrc = d_htb + (size_t)b * CDIM * NTOK + t * KT;
        #pragma unroll
        for (int k2 = 0; k2 < 4; k2++) {
            const int i  = tid + k2 * 128;
            const int ch = i >> 3, ck = i & 7;
            cp16(&hS[buf][ch * 72 + ck * 8], hsrc + (size_t)ch * NTOK + ck * 8);
        }
        CP_COMMIT();
    };

    load_tile(0);

    for (int t = 0; t < NTILE; t++) {
        CP_WAIT0();
        __syncthreads();                       // tile t visible; buf (t+1)&1 free
        if (t + 1 < NTILE) load_tile(t + 1);   // overlaps with compute below

        const int buf = t & 1;

        // --- QK: S[16q x 64k], 8 n-tiles of m16n8k8 ---
        float S[8][4];
        #pragma unroll
        for (int n = 0; n < 8; n++) {
            const uint32_t fb0 = *reinterpret_cast<const uint32_t*>(
                &fS[buf][(n * 8 + gid) * CF + tig * 2]);
            MMA1688(S[n], ga0, ga1, fb0, zc);
        }

        // --- exp + row sums + pack P fragments ---
        uint32_t P[8][2];
        #pragma unroll
        for (int n = 0; n < 8; n++) {
            const float e0 = __expf(S[n][0]);
            const float e1 = __expf(S[n][1]);
            const float e2 = __expf(S[n][2]);
            const float e3 = __expf(S[n][3]);
            l0 += e0 + e1;
            l1 += e2 + e3;
            CVT_BF16X2(P[n][0], e0, e1);
            CVT_BF16X2(P[n][1], e2, e3);
        }

        // --- PV: O[16q x 64c] += P @ H^T, K=64 in 4 k16 chunks ---
        #pragma unroll
        for (int kk = 0; kk < 4; kk++) {
            const uint32_t a0 = P[2 * kk][0];
            const uint32_t a1 = P[2 * kk][1];
            const uint32_t a2 = P[2 * kk + 1][0];
            const uint32_t a3 = P[2 * kk + 1][1];
            #pragma unroll
            for (int nch = 0; nch < 8; nch++) {
                const __nv_bfloat16* hp = &hS[buf][(nch * 8 + gid) * 72 + kk * 16 + tig * 2];
                const uint32_t b0 = *reinterpret_cast<const uint32_t*>(hp);
                const uint32_t b1 = *reinterpret_cast<const uint32_t*>(hp + 8);
                MMA16816(O[nch], a0, a1, a2, a3, b0, b1, O[nch]);
            }
        }
        __syncthreads();   // all warps done with buf before its next overwrite completes
    }

    // reduce row sums across the 4 lanes of each row group
    l0 += __shfl_xor_sync(0xFFFFFFFF, l0, 1);
    l0 += __shfl_xor_sync(0xFFFFFFFF, l0, 2);
    l1 += __shfl_xor_sync(0xFFFFFFFF, l1, 1);
    l1 += __shfl_xor_sync(0xFFFFFFFF, l1, 2);

    const float gm   = gamma[0];
    const float inv0 = gm / l0;
    const float inv1 = gm / l1;

    const size_t base0 = (size_t)(row0 + gid) * CDIM;
    const size_t base1 = (size_t)(row0 + 8 + gid) * CDIM;
    #pragma unroll
    for (int n = 0; n < 8; n++) {
        const int ch = n * 8 + tig * 2;
        const float2 xv0 = *reinterpret_cast<const float2*>(x + base0 + ch);
        const float2 xv1 = *reinterpret_cast<const float2*>(x + base1 + ch);
        float2 o0, o1;
        o0.x = fmaf(inv0, O[n][0], xv0.x);
        o0.y = fmaf(inv0, O[n][1], xv0.y);
        o1.x = fmaf(inv1, O[n][2], xv1.x);
        o1.y = fmaf(inv1, O[n][3], xv1.y);
        *reinterpret_cast<float2*>(out + base0 + ch) = o0;
        *reinterpret_cast<float2*>(out + base1 + ch) = o1;
    }
}

// ---------------- launch ----------------
extern "C" void kernel_launch(void* const* d_in, const int* in_sizes, int n_in,
                              void* d_out, int out_size) {
    const float* x     = (const float*)d_in[0];
    const float* w_f   = (const float*)d_in[1];
    const float* b_f   = (const float*)d_in[2];
    const float* w_g   = (const float*)d_in[3];
    const float* b_g   = (const float*)d_in[4];
    const float* w_h   = (const float*)d_in[5];
    const float* b_h   = (const float*)d_in[6];
    const float* gamma = (const float*)d_in[7];
    float* out = (float*)d_out;

    proj_kernel<<<BN / 32, 256>>>(x, w_f, b_f, w_g, b_g, w_h, b_h);
    attn_kernel<<<dim3(NTOK / QPC, BATCH), 128>>>(x, gamma, out);
}

// round 9
// speedup vs baseline: 5.1175x; 1.0565x over previous
#include <cuda_runtime.h>
#include <cuda_bf16.h>
#include <cstdint>

// Problem: B=4, N=4096 (64x64), C=64, Cf=8
#define BATCH 4
#define NTOK  4096
#define CDIM  64
#define CF    8
#define BN    (BATCH * NTOK)
#define KT    64               // keys per tile
#define NTILE (NTOK / KT)      // 64
#define QPC   64               // queries per CTA (4 warps x 16)
#define HP    72               // hS pitch (elements) - conflict-free for ldmatrix
#define STG   4                // cp.async pipeline stages

// ---------------- scratch (no cudaMalloc allowed) ----------------
__device__ __nv_bfloat16 d_fb[BN * CF];              // keys    [B,N,8]
__device__ __nv_bfloat16 d_gb[BN * CF];              // queries [B,N,8]
__device__ __nv_bfloat16 d_htb[BATCH * CDIM * NTOK]; // values transposed [B,C,N]

#define MMA16816(d, a0, a1, a2, a3, b0, b1, c) \
    asm volatile("mma.sync.aligned.m16n8k16.row.col.f32.bf16.bf16.f32 " \
        "{%0,%1,%2,%3}, {%4,%5,%6,%7}, {%8,%9}, {%10,%11,%12,%13};" \
        : "=f"((d)[0]), "=f"((d)[1]), "=f"((d)[2]), "=f"((d)[3]) \
        : "r"(a0), "r"(a1), "r"(a2), "r"(a3), "r"(b0), "r"(b1), \
          "f"((c)[0]), "f"((c)[1]), "f"((c)[2]), "f"((c)[3]))

#define MMA1688(d, a0, a1, b0, c) \
    asm volatile("mma.sync.aligned.m16n8k8.row.col.f32.bf16.bf16.f32 " \
        "{%0,%1,%2,%3}, {%4,%5}, {%6}, {%7,%8,%9,%10};" \
        : "=f"((d)[0]), "=f"((d)[1]), "=f"((d)[2]), "=f"((d)[3]) \
        : "r"(a0), "r"(a1), "r"(b0), \
          "f"((c)[0]), "f"((c)[1]), "f"((c)[2]), "f"((c)[3]))

#define CVT_BF16X2(res, lo, hi) \
    asm("cvt.rn.bf16x2.f32 %0, %1, %2;" : "=r"(res) : "f"(hi), "f"(lo))

__device__ __forceinline__ void cp16(void* dst, const void* src) {
    const uint32_t d = (uint32_t)__cvta_generic_to_shared(dst);
    asm volatile("cp.async.cg.shared.global [%0], [%1], 16;" :: "r"(d), "l"(src));
}
#define CP_COMMIT() asm volatile("cp.async.commit_group;" ::: "memory")
#define CP_WAIT2()  asm volatile("cp.async.wait_group 2;" ::: "memory")

__device__ __forceinline__ void ldmat4(uint32_t& r0, uint32_t& r1, uint32_t& r2,
                                       uint32_t& r3, const void* p) {
    const uint32_t a = (uint32_t)__cvta_generic_to_shared(p);
    asm volatile("ldmatrix.sync.aligned.m8n8.x4.shared.b16 {%0,%1,%2,%3}, [%4];"
                 : "=r"(r0), "=r"(r1), "=r"(r2), "=r"(r3) : "r"(a));
}

// ---------------- kernel 1: fused projections -> bf16 ----------------
__global__ void proj_kernel(const float* __restrict__ x,
                            const float* __restrict__ w_f, const float* __restrict__ b_f,
                            const float* __restrict__ w_g, const float* __restrict__ b_g,
                            const float* __restrict__ w_h, const float* __restrict__ b_h) {
    __shared__ float wf_s[CDIM * CF];
    __shared__ float wg_s[CDIM * CF];
    __shared__ float wh_s[CDIM * CDIM];
    __shared__ float bf_s[CF], bg_s[CF], bh_s[CDIM];
    __shared__ float xs[32][CDIM];
    __shared__ float hs[CDIM][33];

    const int tid = threadIdx.x;
    for (int i = tid; i < CDIM * CF; i += 256) { wf_s[i] = w_f[i]; wg_s[i] = w_g[i]; }
    for (int i = tid; i < CDIM * CDIM; i += 256) wh_s[i] = w_h[i];
    if (tid < CF)   { bf_s[tid] = b_f[tid]; bg_s[tid] = b_g[tid]; }
    if (tid < CDIM) bh_s[tid] = b_h[tid];

    const int row0 = blockIdx.x * 32;
    for (int i = tid; i < 32 * CDIM; i += 256)
        xs[i / CDIM][i % CDIM] = x[(row0 + i / CDIM) * CDIM + (i % CDIM)];
    __syncthreads();

    for (int idx = tid; idx < 32 * 80; idx += 256) {
        const int r = idx / 80, c = idx % 80;
        const float* w; float bias; int stride;
        if (c < 8)       { w = wf_s + c;        bias = bf_s[c];      stride = CF;   }
        else if (c < 16) { w = wg_s + (c - 8);  bias = bg_s[c - 8];  stride = CF;   }
        else             { w = wh_s + (c - 16); bias = bh_s[c - 16]; stride = CDIM; }
        float acc = bias;
        #pragma unroll
        for (int k = 0; k < CDIM; k++) acc += xs[r][k] * w[k * stride];
        const int row = row0 + r;
        if (c < 8)       d_fb[row * CF + c] = __float2bfloat16(acc);
        else if (c < 16) d_gb[row * CF + (c - 8)] = __float2bfloat16(acc);
        else             hs[c - 16][r] = acc;
    }
    __syncthreads();

    {
        const int b  = row0 >> 12;
        const int n0 = row0 & (NTOK - 1);
        const int ch = tid >> 2;
        const int part = (tid & 3) * 8;
        __nv_bfloat16 v[8];
        #pragma unroll
        for (int j = 0; j < 8; j++) v[j] = __float2bfloat16(hs[ch][part + j]);
        *reinterpret_cast<uint4*>(d_htb + ((size_t)b * CDIM + ch) * NTOK + n0 + part) =
            *reinterpret_cast<const uint4*>(v);
    }
}

// ---------------- kernel 2: HMMA flash attention ----------------
// 4 warps x 16 queries; grid (64,4)=256 CTAs (~2/SM).
// 4-stage cp.async ring (1 sync/tile), ldmatrix.x4 for all B fragments.
__global__ __launch_bounds__(128, 2)
void attn_kernel(const float* __restrict__ x,
                 const float* __restrict__ gamma,
                 float* __restrict__ out) {
    __shared__ __nv_bfloat16 fS[STG][KT * CF];    // 1 KB per stage
    __shared__ __nv_bfloat16 hS[STG][CDIM * HP];  // 9 KB per stage

    const int tid  = threadIdx.x;
    const int warp = tid >> 5;
    const int lane = tid & 31;
    const int gid  = lane >> 2;
    const int tig  = lane & 3;
    const int mat  = lane >> 3;    // ldmatrix matrix id 0..3
    const int mrow = lane & 7;     // ldmatrix row within matrix

    const int b    = blockIdx.y;
    const int q0   = blockIdx.x * QPC + warp * 16;
    const int row0 = b * NTOK + q0;

    // per-thread ldmatrix base offsets (elements)
    const int f_off = (mat * 8 + mrow) * CF;                     // key row, 16B rows
    const int h_off = ((mat >> 1) * 8 + mrow) * HP + (mat & 1) * 8;

    const uint32_t ga0 = *reinterpret_cast<const uint32_t*>(d_gb + (row0 + gid) * CF + tig * 2);
    const uint32_t ga1 = *reinterpret_cast<const uint32_t*>(d_gb + (row0 + 8 + gid) * CF + tig * 2);

    float O[8][4];
    #pragma unroll
    for (int n = 0; n < 8; n++)
        #pragma unroll
        for (int j = 0; j < 4; j++) O[n][j] = 0.0f;
    float l0 = 0.0f, l1 = 0.0f;
    const float zc[4] = {0.0f, 0.0f, 0.0f, 0.0f};

    auto load_tile = [&](int t) {
        const int buf = t & (STG - 1);
        if (tid < 64)
            cp16(&fS[buf][tid * CF], d_fb + (size_t)(b * NTOK + t * KT + tid) * CF);
        const __nv_bfloat16* hsrc = d_htb + (size_t)b * CDIM * NTOK + t * KT;
        #pragma unroll
        for (int k2 = 0; k2 < 4; k2++) {
            const int i  = tid + k2 * 128;
            const int ch = i >> 3, ck = i & 7;
            cp16(&hS[buf][ch * HP + ck * 8], hsrc + (size_t)ch * NTOK + ck * 8);
        }
    };

    load_tile(0); CP_COMMIT();
    load_tile(1); CP_COMMIT();
    load_tile(2); CP_COMMIT();

    for (int t = 0; t < NTILE; t++) {
        CP_WAIT2();                 // group t complete (in-order, <=2 newer pending)
        __syncthreads();            // all warps see tile t; all done reading buf (t-1)&3
        if (t + 3 < NTILE) load_tile(t + 3);   // writes buf (t-1)&3 — safe
        CP_COMMIT();                // keep group-count invariant (empty ok)

        const int buf = t & (STG - 1);

        // --- QK: S[16q x 64k], 8 n-tiles, B frags via 2x ldmatrix.x4 ---
        float S[8][4];
        {
            uint32_t fb[8];
            ldmat4(fb[0], fb[1], fb[2], fb[3], &fS[buf][f_off]);
            ldmat4(fb[4], fb[5], fb[6], fb[7], &fS[buf][f_off + 32 * CF]);
            #pragma unroll
            for (int n = 0; n < 8; n++) MMA1688(S[n], ga0, ga1, fb[n], zc);
        }

        // --- exp + row sums + pack P fragments ---
        uint32_t P[8][2];
        #pragma unroll
        for (int n = 0; n < 8; n++) {
            const float e0 = __expf(S[n][0]);
            const float e1 = __expf(S[n][1]);
            const float e2 = __expf(S[n][2]);
            const float e3 = __expf(S[n][3]);
            l0 += e0 + e1;
            l1 += e2 + e3;
            CVT_BF16X2(P[n][0], e0, e1);
            CVT_BF16X2(P[n][1], e2, e3);
        }

        // --- PV: O += P @ H^T, K=64; B frags via ldmatrix.x4 (2 MMAs each) ---
        #pragma unroll
        for (int kk = 0; kk < 4; kk++) {
            const uint32_t a0 = P[2 * kk][0];
            const uint32_t a1 = P[2 * kk][1];
            const uint32_t a2 = P[2 * kk + 1][0];
            const uint32_t a3 = P[2 * kk + 1][1];
            #pragma unroll
            for (int np = 0; np < 4; np++) {
                uint32_t b0, b1, b2, b3;
                ldmat4(b0, b1, b2, b3, &hS[buf][h_off + np * 16 * HP + kk * 16]);
                MMA16816(O[2 * np],     a0, a1, a2, a3, b0, b1, O[2 * np]);
                MMA16816(O[2 * np + 1], a0, a1, a2, a3, b2, b3, O[2 * np + 1]);
            }
        }
    }

    l0 += __shfl_xor_sync(0xFFFFFFFF, l0, 1);
    l0 += __shfl_xor_sync(0xFFFFFFFF, l0, 2);
    l1 += __shfl_xor_sync(0xFFFFFFFF, l1, 1);
    l1 += __shfl_xor_sync(0xFFFFFFFF, l1, 2);

    const float gm   = gamma[0];
    const float inv0 = gm / l0;
    const float inv1 = gm / l1;

    const size_t base0 = (size_t)(row0 + gid) * CDIM;
    const size_t base1 = (size_t)(row0 + 8 + gid) * CDIM;
    #pragma unroll
    for (int n = 0; n < 8; n++) {
        const int ch = n * 8 + tig * 2;
        const float2 xv0 = *reinterpret_cast<const float2*>(x + base0 + ch);
        const float2 xv1 = *reinterpret_cast<const float2*>(x + base1 + ch);
        float2 o0, o1;
        o0.x = fmaf(inv0, O[n][0], xv0.x);
        o0.y = fmaf(inv0, O[n][1], xv0.y);
        o1.x = fmaf(inv1, O[n][2], xv1.x);
        o1.y = fmaf(inv1, O[n][3], xv1.y);
        *reinterpret_cast<float2*>(out + base0 + ch) = o0;
        *reinterpret_cast<float2*>(out + base1 + ch) = o1;
    }
}

// ---------------- launch ----------------
extern "C" void kernel_launch(void* const* d_in, const int* in_sizes, int n_in,
                              void* d_out, int out_size) {
    const float* x     = (const float*)d_in[0];
    const float* w_f   = (const float*)d_in[1];
    const float* b_f   = (const float*)d_in[2];
    const float* w_g   = (const float*)d_in[3];
    const float* b_g   = (const float*)d_in[4];
    const float* w_h   = (const float*)d_in[5];
    const float* b_h   = (const float*)d_in[6];
    const float* gamma = (const float*)d_in[7];
    float* out = (float*)d_out;

    proj_kernel<<<BN / 32, 256>>>(x, w_f, b_f, w_g, b_g, w_h, b_h);
    attn_kernel<<<dim3(NTOK / QPC, BATCH), 128>>>(x, gamma, out);
}